// round 11
// baseline (speedup 1.0000x reference)
#include <cuda_runtime.h>
#include <cstdint>

// Problem constants
#define BATCH 32
#define CIN   128
#define COUT  256
#define HH    56
#define WW    56
#define HWPix (HH*WW)          // 3136
#define KTAPS 9
#define KTOT  (CIN*KTAPS)      // 1152

#define PA 144                 // A smem pitch (bytes), LDSM conflict-free
#define ABUF (128*PA)          // 18432 per tap slab
#define SMEMSZ (KTAPS*ABUF)    // 165888 : all 9 tap slabs resident

// Scratch (allocation-free rule: __device__ globals)
__device__ __align__(128) int8_t g_x8[(size_t)BATCH * HWPix * CIN];     // NHWC int8
// Weights v2 fragment order: [ntile 32][tap 9][lane 32][kc 4] x 8B
__device__ __align__(128) int8_t g_wfrag[32 * KTAPS * 32 * 4 * 8];      // 294912 B

// ---------------------------------------------------------------------------
// Kernel 1: merged converts.
//   blocks [0,392): x fp32 NCHW -> int8 NHWC, thread per pixel.
//   blocks [392,536): w fp32 OIHW -> fragment-ordered int8 (layout v2).
// ---------------------------------------------------------------------------
__global__ void convert_kernel(const float* __restrict__ x,
                               const float* __restrict__ w) {
    if (blockIdx.x < 392) {
        int p  = blockIdx.x * 256 + threadIdx.x;      // 0 .. 100351
        int b  = p / HWPix;
        int hw = p - b * HWPix;
        const float* xb = x + (size_t)b * CIN * HWPix + hw;
        uint32_t pk[32];
#pragma unroll
        for (int c = 0; c < CIN; c += 4) {
            uint32_t v = 0;
#pragma unroll
            for (int k = 0; k < 4; k++) {
                int val = __float2int_rn(xb[(size_t)(c + k) * HWPix]);
                v |= (uint32_t)(val & 0xFF) << (8 * k);
            }
            pk[c >> 2] = v;
        }
        int4* dst = (int4*)(g_x8 + (size_t)p * CIN);
#pragma unroll
        for (int i = 0; i < 8; i++)
            dst[i] = make_int4((int)pk[4*i], (int)pk[4*i+1], (int)pk[4*i+2], (int)pk[4*i+3]);
    } else {
        // v2 entry t = ((nt*9 + tap)*32 + lane)*4 + kc ; 8B per entry.
        // lane (g=lane>>2, tig=lane&3) holds bytes W[n=nt*8+g][tap][c=kc*32+4*tig+j]
        // (j=0..3) in v0 and the same with c+16 in v1.
        int t = (blockIdx.x - 392) * 256 + threadIdx.x;   // 0 .. 36863
        if (t < 32 * KTAPS * 32 * 4) {
            int nt   = t / (KTAPS * 32 * 4);
            int r    = t - nt * (KTAPS * 32 * 4);
            int tap  = r / (32 * 4);
            int r2   = r - tap * (32 * 4);
            int lane = r2 >> 2;
            int kc   = r2 & 3;
            int g    = lane >> 2, tig = lane & 3;
            int n    = nt * 8 + g;
            uint32_t v0 = 0, v1 = 0;
#pragma unroll
            for (int j = 0; j < 4; j++) {
                int c0 = kc * 32 + 4 * tig + j;
                int val0 = __float2int_rn(w[((size_t)(n * CIN + c0)) * KTAPS + tap]);
                int val1 = __float2int_rn(w[((size_t)(n * CIN + c0 + 16)) * KTAPS + tap]);
                v0 |= (uint32_t)(val0 & 0xFF) << (8 * j);
                v1 |= (uint32_t)(val1 & 0xFF) << (8 * j);
            }
            int2* dst = (int2*)(g_wfrag + (size_t)t * 8);
            *dst = make_int2((int)v0, (int)v1);
        }
    }
}

// ---------------------------------------------------------------------------
// Kernel 2: implicit-GEMM conv. CTA tile M=128 x N=256, 256 threads
// (8 warps as 2M x 4N, warp tile 64x64). All 9 A-tap slabs resident in smem
// (9 commit groups, per-tap wait). Weights: 2 x LDG.128 per (tn,tap) covering
// all 4 kc, software-pipelined one tn ahead.
// ---------------------------------------------------------------------------
__device__ __forceinline__ void mma_s8(int* c, const int* a, int b0, int b1) {
    asm volatile(
        "mma.sync.aligned.m16n8k32.row.col.s32.s8.s8.s32 "
        "{%0,%1,%2,%3}, {%4,%5,%6,%7}, {%8,%9}, {%0,%1,%2,%3};\n"
        : "+r"(c[0]), "+r"(c[1]), "+r"(c[2]), "+r"(c[3])
        : "r"(a[0]), "r"(a[1]), "r"(a[2]), "r"(a[3]), "r"(b0), "r"(b1));
}

#define CPA16(dst, src, sz) \
    asm volatile("cp.async.cg.shared.global [%0], [%1], 16, %2;\n" \
                 :: "r"(dst), "l"(src), "r"(sz))

__global__ void __launch_bounds__(256, 1)
conv_mma_kernel(const float* __restrict__ tbias,
                const int*   __restrict__ nshift,
                const int*   __restrict__ amin,
                const int*   __restrict__ amax,
                float*       __restrict__ out) {
    extern __shared__ __align__(16) int8_t smA[];
    const uint32_t smem_u32 = (uint32_t)__cvta_generic_to_shared(smA);

    const int tid  = threadIdx.x;
    const int lane = tid & 31;
    const int warp = tid >> 5;
    const int warpM = warp >> 2;         // 0..1 -> 64 M-rows each
    const int warpN = warp & 3;          // 0..3 -> 64 N-cols (8 n8-tiles)
    const int g   = lane >> 2;
    const int tig = lane & 3;

    const int m0 = blockIdx.x * 128;     // may span batch boundary (handled per-row)

    // A-loader invariants: row = tid>>1 (0..127), half = tid&1 (64B each)
    const int ar = tid >> 1, ahalf = tid & 1;
    const int ap  = m0 + ar;
    const int ab  = ap / HWPix;
    const int ahw = ap - ab * HWPix;
    const int ah  = ahw / WW;
    const int aw  = ahw - ah * WW;

    // ---- issue ALL 9 tap slabs, one commit group per tap ----
#pragma unroll
    for (int tap = 0; tap < KTAPS; tap++) {
        const int dh = tap / 3 - 1;
        const int dw = tap % 3 - 1;
        int hs = ah + dh, ws = aw + dw;
        bool valid = ((unsigned)hs < HH) && ((unsigned)ws < WW);
        int sidx = valid ? (ab * HWPix + hs * WW + ws) : 0;
        const int8_t* src = g_x8 + ((size_t)sidx << 7) + ahalf * 64;
        uint32_t dst = smem_u32 + tap * ABUF + ar * PA + ahalf * 64;
        int sz = valid ? 16 : 0;
#pragma unroll
        for (int c = 0; c < 4; c++)
            CPA16(dst + c * 16, src + c * 16, sz);
        asm volatile("cp.async.commit_group;\n");
    }

    int acc[4][8][4];
#pragma unroll
    for (int i = 0; i < 4; i++)
#pragma unroll
        for (int j = 0; j < 8; j++)
#pragma unroll
            for (int k = 0; k < 4; k++) acc[i][j][k] = 0;

    // W base for this warp's tn=0 tile (nt = warpN*8); per-nt stride 9216 B.
    // byte offset(tn, tap) = (((warpN*8+tn)*9 + tap)*32 + lane)*32
    const int8_t* wbase = g_wfrag
        + ((size_t)(warpN * 8) * KTAPS + 0) * 1024 + (size_t)lane * 32;

    // ---- mainloop over taps ----
#pragma unroll 1
    for (int tap = 0; tap < KTAPS; tap++) {
        // wait for this tap's slab (groups land in issue order)
        switch (tap) {
            case 0: asm volatile("cp.async.wait_group 8;\n"); break;
            case 1: asm volatile("cp.async.wait_group 7;\n"); break;
            case 2: asm volatile("cp.async.wait_group 6;\n"); break;
            case 3: asm volatile("cp.async.wait_group 5;\n"); break;
            case 4: asm volatile("cp.async.wait_group 4;\n"); break;
            case 5: asm volatile("cp.async.wait_group 3;\n"); break;
            case 6: asm volatile("cp.async.wait_group 2;\n"); break;
            case 7: asm volatile("cp.async.wait_group 1;\n"); break;
            default: asm volatile("cp.async.wait_group 0;\n"); break;
        }
        __syncthreads();

        // A fragments for all 4 mi x 4 kc
        int a[4][4][4];
        const uint32_t baseA = smem_u32 + tap * ABUF;
#pragma unroll
        for (int mi = 0; mi < 4; mi++) {
#pragma unroll
            for (int kc = 0; kc < 4; kc++) {
                int row = warpM * 64 + mi * 16 + (lane & 15);
                int col = kc * 32 + ((lane >> 4) << 4);
                uint32_t addr = baseA + row * PA + col;
                asm volatile(
                    "ldmatrix.sync.aligned.m8n8.x4.shared.b16 {%0,%1,%2,%3}, [%4];\n"
                    : "=r"(a[mi][kc][0]), "=r"(a[mi][kc][1]),
                      "=r"(a[mi][kc][2]), "=r"(a[mi][kc][3])
                    : "r"(addr));
            }
        }

        // weight-pipelined tn loop: 2 x LDG.128 per tn covers all 4 kc
        const int8_t* wt = wbase + (size_t)tap * 1024;
        int4 w0 = __ldg((const int4*)(wt));
        int4 w1 = __ldg((const int4*)(wt + 16));
#pragma unroll
        for (int tn = 0; tn < 8; tn++) {
            int4 n0, n1;
            if (tn < 7) {
                const int8_t* wn = wt + (size_t)(tn + 1) * (KTAPS * 1024);
                n0 = __ldg((const int4*)(wn));
                n1 = __ldg((const int4*)(wn + 16));
            }
#pragma unroll
            for (int mi = 0; mi < 4; mi++) {
                mma_s8(acc[mi][tn], a[mi][0], w0.x, w0.y);
                mma_s8(acc[mi][tn], a[mi][1], w0.z, w0.w);
                mma_s8(acc[mi][tn], a[mi][2], w1.x, w1.y);
                mma_s8(acc[mi][tn], a[mi][3], w1.z, w1.w);
            }
            if (tn < 7) { w0 = n0; w1 = n1; }
        }
    }

    // ---- epilogue: bias + arithmetic shift + clamp -> float32 out ----
    float* rowbase[4][2];
#pragma unroll
    for (int mi = 0; mi < 4; mi++) {
#pragma unroll
        for (int rh = 0; rh < 2; rh++) {
            int ml = warpM * 64 + mi * 16 + rh * 8 + g;
            int p  = m0 + ml;
            int bo = p / HWPix;
            int hwo = p - bo * HWPix;
            rowbase[mi][rh] = out + (size_t)bo * COUT * HWPix + hwo;
        }
    }
#pragma unroll
    for (int tn = 0; tn < 8; tn++) {
#pragma unroll
        for (int cb = 0; cb < 2; cb++) {
            int ng = warpN * 64 + tn * 8 + 2 * tig + cb;
            int tb = __float2int_rn(__ldg(&tbias[ng]));
            int sh = -__ldg(&nshift[ng]);
            int mn = __ldg(&amin[ng]);
            int mx = __ldg(&amax[ng]);
#pragma unroll
            for (int mi = 0; mi < 4; mi++) {
#pragma unroll
                for (int rh = 0; rh < 2; rh++) {
                    int v = acc[mi][tn][rh * 2 + cb];
                    v = (v + tb) >> sh;
                    v = max(mn, min(mx, v));
                    rowbase[mi][rh][(size_t)ng * HWPix] = (float)v;
                }
            }
        }
    }
}

// ---------------------------------------------------------------------------
// Launch
// ---------------------------------------------------------------------------
extern "C" void kernel_launch(void* const* d_in, const int* in_sizes, int n_in,
                              void* d_out, int out_size) {
    const float* x      = (const float*)d_in[0];
    const float* weight = (const float*)d_in[1];
    const float* tbias  = (const float*)d_in[2];
    const int*   nsh    = (const int*)d_in[3];
    const int*   amin   = (const int*)d_in[4];
    const int*   amax   = (const int*)d_in[5];
    float* out = (float*)d_out;

    (void)cudaFuncSetAttribute(conv_mma_kernel,
                               cudaFuncAttributeMaxDynamicSharedMemorySize,
                               SMEMSZ);

    convert_kernel<<<536, 256>>>(x, weight);                       // 392 + 144 blocks
    conv_mma_kernel<<<(BATCH * HWPix) / 128, 256, SMEMSZ>>>(tbias, nsh, amin, amax, out);
}

// round 12
// speedup vs baseline: 1.2708x; 1.2708x over previous
#include <cuda_runtime.h>
#include <cstdint>

// Problem constants
#define BATCH 32
#define CIN   128
#define COUT  256
#define HH    56
#define WW    56
#define HWPix (HH*WW)          // 3136
#define KTAPS 9
#define KTOT  (CIN*KTAPS)      // 1152

#define PA 144                 // A smem pitch (bytes), LDSM conflict-free
#define ABUF (64*PA)           // 9216 per tap slab (M=64 tile)
#define SMEMSZ (KTAPS*ABUF)    // 82944 : all 9 tap slabs resident, 2 CTAs/SM

// Scratch (allocation-free rule: __device__ globals)
__device__ __align__(128) int8_t g_x8[(size_t)BATCH * HWPix * CIN];     // NHWC int8
// Weights v2 fragment order: [ntile 32][tap 9][lane 32][kc 4] x 8B
__device__ __align__(128) int8_t g_wfrag[32 * KTAPS * 32 * 4 * 8];      // 294912 B

// ---------------------------------------------------------------------------
// Kernel 1: merged converts.
//   blocks [0,392): x fp32 NCHW -> int8 NHWC, thread per pixel.
//   blocks [392,536): w fp32 OIHW -> fragment-ordered int8 (layout v2).
// ---------------------------------------------------------------------------
__global__ void convert_kernel(const float* __restrict__ x,
                               const float* __restrict__ w) {
    if (blockIdx.x < 392) {
        int p  = blockIdx.x * 256 + threadIdx.x;      // 0 .. 100351
        int b  = p / HWPix;
        int hw = p - b * HWPix;
        const float* xb = x + (size_t)b * CIN * HWPix + hw;
        uint32_t pk[32];
#pragma unroll
        for (int c = 0; c < CIN; c += 4) {
            uint32_t v = 0;
#pragma unroll
            for (int k = 0; k < 4; k++) {
                int val = __float2int_rn(xb[(size_t)(c + k) * HWPix]);
                v |= (uint32_t)(val & 0xFF) << (8 * k);
            }
            pk[c >> 2] = v;
        }
        int4* dst = (int4*)(g_x8 + (size_t)p * CIN);
#pragma unroll
        for (int i = 0; i < 8; i++)
            dst[i] = make_int4((int)pk[4*i], (int)pk[4*i+1], (int)pk[4*i+2], (int)pk[4*i+3]);
    } else {
        // v2 entry t = ((nt*9 + tap)*32 + lane)*4 + kc ; 8B per entry.
        // lane (g=lane>>2, tig=lane&3) holds bytes W[n=nt*8+g][tap][c=kc*32+4*tig+j]
        // (j=0..3) in v0 and the same with c+16 in v1.
        int t = (blockIdx.x - 392) * 256 + threadIdx.x;   // 0 .. 36863
        if (t < 32 * KTAPS * 32 * 4) {
            int nt   = t / (KTAPS * 32 * 4);
            int r    = t - nt * (KTAPS * 32 * 4);
            int tap  = r / (32 * 4);
            int r2   = r - tap * (32 * 4);
            int lane = r2 >> 2;
            int kc   = r2 & 3;
            int g    = lane >> 2, tig = lane & 3;
            int n    = nt * 8 + g;
            uint32_t v0 = 0, v1 = 0;
#pragma unroll
            for (int j = 0; j < 4; j++) {
                int c0 = kc * 32 + 4 * tig + j;
                int val0 = __float2int_rn(w[((size_t)(n * CIN + c0)) * KTAPS + tap]);
                int val1 = __float2int_rn(w[((size_t)(n * CIN + c0 + 16)) * KTAPS + tap]);
                v0 |= (uint32_t)(val0 & 0xFF) << (8 * j);
                v1 |= (uint32_t)(val1 & 0xFF) << (8 * j);
            }
            int2* dst = (int2*)(g_wfrag + (size_t)t * 8);
            *dst = make_int2((int)v0, (int)v1);
        }
    }
}

// ---------------------------------------------------------------------------
// Kernel 2: implicit-GEMM conv. CTA tile M=64 x N=256, 256 threads
// (8 warps as 2M x 4N, warp tile 32x64). All 9 A-tap slabs resident in smem,
// per-tap commit groups + progressive waits. Weights: v2 layout, 2 x LDG.128
// per (tn,tap) covering all 4 kc, pipelined one tn ahead. 2 CTAs/SM.
// ---------------------------------------------------------------------------
__device__ __forceinline__ void mma_s8(int* c, const int* a, int b0, int b1) {
    asm volatile(
        "mma.sync.aligned.m16n8k32.row.col.s32.s8.s8.s32 "
        "{%0,%1,%2,%3}, {%4,%5,%6,%7}, {%8,%9}, {%0,%1,%2,%3};\n"
        : "+r"(c[0]), "+r"(c[1]), "+r"(c[2]), "+r"(c[3])
        : "r"(a[0]), "r"(a[1]), "r"(a[2]), "r"(a[3]), "r"(b0), "r"(b1));
}

#define CPA16(dst, src, sz) \
    asm volatile("cp.async.cg.shared.global [%0], [%1], 16, %2;\n" \
                 :: "r"(dst), "l"(src), "r"(sz))

__global__ void __launch_bounds__(256, 2)
conv_mma_kernel(const float* __restrict__ tbias,
                const int*   __restrict__ nshift,
                const int*   __restrict__ amin,
                const int*   __restrict__ amax,
                float*       __restrict__ out) {
    extern __shared__ __align__(16) int8_t smA[];
    const uint32_t smem_u32 = (uint32_t)__cvta_generic_to_shared(smA);

    const int tid  = threadIdx.x;
    const int lane = tid & 31;
    const int warp = tid >> 5;
    const int warpM = warp >> 2;         // 0..1 -> 32 M-rows each
    const int warpN = warp & 3;          // 0..3 -> 64 N-cols (8 n8-tiles)
    const int g   = lane >> 2;
    const int tig = lane & 3;

    const int m0  = blockIdx.x * 64;     // 3136 % 64 == 0 -> tile never spans batch
    const int b   = m0 / HWPix;
    const int hw0 = m0 - b * HWPix;

    // A-loader invariants: row = tid>>2 (0..63), quarter = tid&3 (32B each)
    const int ar = tid >> 2, aq = tid & 3;
    const int ahw = hw0 + ar;
    const int ah  = ahw / WW;
    const int aw  = ahw - ah * WW;

    // ---- issue ALL 9 tap slabs, one commit group per tap ----
#pragma unroll
    for (int tap = 0; tap < KTAPS; tap++) {
        const int dh = tap / 3 - 1;
        const int dw = tap % 3 - 1;
        int hs = ah + dh, ws = aw + dw;
        bool valid = ((unsigned)hs < HH) && ((unsigned)ws < WW);
        int sidx = valid ? (b * HWPix + hs * WW + ws) : 0;
        const int8_t* src = g_x8 + ((size_t)sidx << 7) + aq * 32;
        uint32_t dst = smem_u32 + tap * ABUF + ar * PA + aq * 32;
        int sz = valid ? 16 : 0;
        CPA16(dst,      src,      sz);
        CPA16(dst + 16, src + 16, sz);
        asm volatile("cp.async.commit_group;\n");
    }

    int acc[2][8][4];
#pragma unroll
    for (int i = 0; i < 2; i++)
#pragma unroll
        for (int j = 0; j < 8; j++)
#pragma unroll
            for (int k = 0; k < 4; k++) acc[i][j][k] = 0;

    // W base for this warp: nt = warpN*8 + tn. v2 strides: nt 9216B, tap 1024B.
    const int8_t* wbase = g_wfrag + (size_t)(warpN * 8) * (KTAPS * 1024)
                        + (size_t)lane * 32;

    // ---- mainloop over taps (no in-loop barriers; slabs are read-only) ----
#pragma unroll 1
    for (int tap = 0; tap < KTAPS; tap++) {
        // progressive wait: this tap's group has landed when <= (8-tap) pending
        switch (tap) {
            case 0: asm volatile("cp.async.wait_group 8;\n"); break;
            case 1: asm volatile("cp.async.wait_group 7;\n"); break;
            case 2: asm volatile("cp.async.wait_group 6;\n"); break;
            case 3: asm volatile("cp.async.wait_group 5;\n"); break;
            case 4: asm volatile("cp.async.wait_group 4;\n"); break;
            case 5: asm volatile("cp.async.wait_group 3;\n"); break;
            case 6: asm volatile("cp.async.wait_group 2;\n"); break;
            case 7: asm volatile("cp.async.wait_group 1;\n"); break;
            default: asm volatile("cp.async.wait_group 0;\n"); break;
        }
        if (tap == 0) __syncthreads();   // own cp.async visible after wait; others' via first barrier

        // A fragments for all 4 kc (8 LDSM, 32 regs)
        int a[2][4][4];
        const uint32_t baseA = smem_u32 + tap * ABUF;
#pragma unroll
        for (int mi = 0; mi < 2; mi++) {
#pragma unroll
            for (int kc = 0; kc < 4; kc++) {
                int row = warpM * 32 + mi * 16 + (lane & 15);
                int col = kc * 32 + ((lane >> 4) << 4);
                uint32_t addr = baseA + row * PA + col;
                asm volatile(
                    "ldmatrix.sync.aligned.m8n8.x4.shared.b16 {%0,%1,%2,%3}, [%4];\n"
                    : "=r"(a[mi][kc][0]), "=r"(a[mi][kc][1]),
                      "=r"(a[mi][kc][2]), "=r"(a[mi][kc][3])
                    : "r"(addr));
            }
        }

        // weight-pipelined tn loop: 2 x LDG.128 per tn covers all 4 kc
        const int8_t* wt = wbase + (size_t)tap * 1024;
        int4 w0 = __ldg((const int4*)(wt));
        int4 w1 = __ldg((const int4*)(wt + 16));
#pragma unroll
        for (int tn = 0; tn < 8; tn++) {
            int4 n0, n1;
            if (tn < 7) {
                const int8_t* wn = wt + (size_t)(tn + 1) * (KTAPS * 1024);
                n0 = __ldg((const int4*)(wn));
                n1 = __ldg((const int4*)(wn + 16));
            }
#pragma unroll
            for (int mi = 0; mi < 2; mi++) {
                mma_s8(acc[mi][tn], a[mi][0], w0.x, w0.y);
                mma_s8(acc[mi][tn], a[mi][1], w0.z, w0.w);
                mma_s8(acc[mi][tn], a[mi][2], w1.x, w1.y);
                mma_s8(acc[mi][tn], a[mi][3], w1.z, w1.w);
            }
            if (tn < 7) { w0 = n0; w1 = n1; }
        }
    }

    // ---- epilogue: bias + arithmetic shift + clamp -> float32 out ----
#pragma unroll
    for (int tn = 0; tn < 8; tn++) {
#pragma unroll
        for (int cb = 0; cb < 2; cb++) {
            int ng = warpN * 64 + tn * 8 + 2 * tig + cb;
            int tb = __float2int_rn(__ldg(&tbias[ng]));
            int sh = -__ldg(&nshift[ng]);
            int mn = __ldg(&amin[ng]);
            int mx = __ldg(&amax[ng]);
            float* rowp = out + ((size_t)b * COUT + ng) * HWPix + hw0;
#pragma unroll
            for (int mi = 0; mi < 2; mi++) {
#pragma unroll
                for (int rh = 0; rh < 2; rh++) {
                    int v = acc[mi][tn][rh * 2 + cb];
                    v = (v + tb) >> sh;
                    v = max(mn, min(mx, v));
                    int ml = warpM * 32 + mi * 16 + rh * 8 + g;
                    rowp[ml] = (float)v;
                }
            }
        }
    }
}

// ---------------------------------------------------------------------------
// Launch
// ---------------------------------------------------------------------------
extern "C" void kernel_launch(void* const* d_in, const int* in_sizes, int n_in,
                              void* d_out, int out_size) {
    const float* x      = (const float*)d_in[0];
    const float* weight = (const float*)d_in[1];
    const float* tbias  = (const float*)d_in[2];
    const int*   nsh    = (const int*)d_in[3];
    const int*   amin   = (const int*)d_in[4];
    const int*   amax   = (const int*)d_in[5];
    float* out = (float*)d_out;

    (void)cudaFuncSetAttribute(conv_mma_kernel,
                               cudaFuncAttributeMaxDynamicSharedMemorySize,
                               SMEMSZ);

    convert_kernel<<<536, 256>>>(x, weight);                       // 392 + 144 blocks
    conv_mma_kernel<<<BATCH * (HWPix / 64), 256, SMEMSZ>>>(tbias, nsh, amin, amax, out);
}

// round 13
// speedup vs baseline: 1.3485x; 1.0611x over previous
#include <cuda_runtime.h>
#include <cstdint>

// Problem constants
#define BATCH 32
#define CIN   128
#define COUT  256
#define HH    56
#define WW    56
#define HWPix (HH*WW)          // 3136
#define KTAPS 9
#define KTOT  (CIN*KTAPS)      // 1152

#define PA 144                 // A smem pitch (bytes), LDSM conflict-free
#define ABUF (64*PA)           // 9216 per tap slab (M=64 tile)
#define SMEMSZ (KTAPS*ABUF)    // 82944 : all 9 tap slabs resident, 2 CTAs/SM

// Scratch (allocation-free rule: __device__ globals)
__device__ __align__(128) int8_t g_x8[(size_t)BATCH * HWPix * CIN];     // NHWC int8
// Weights v3 fragment order: [ntile 32][tap 9][half 2][lane 32] x 16B
// half h covers kc = 2h (bytes 0:8) and kc = 2h+1 (bytes 8:16).
// Warp LDG.128 at (nt,tap,h) + lane*16 is a contiguous 512B request.
__device__ __align__(128) int8_t g_wfrag[32 * KTAPS * 2 * 32 * 16];     // 294912 B

// ---------------------------------------------------------------------------
// Kernel 1: merged converts.
//   blocks [0,392): x fp32 NCHW -> int8 NHWC, thread per pixel.
//   blocks [392,464): w fp32 OIHW -> fragment-ordered int8 (layout v3),
//                     thread per 16B entry.
// ---------------------------------------------------------------------------
__global__ void convert_kernel(const float* __restrict__ x,
                               const float* __restrict__ w) {
    if (blockIdx.x < 392) {
        int p  = blockIdx.x * 256 + threadIdx.x;      // 0 .. 100351
        int b  = p / HWPix;
        int hw = p - b * HWPix;
        const float* xb = x + (size_t)b * CIN * HWPix + hw;
        uint32_t pk[32];
#pragma unroll
        for (int c = 0; c < CIN; c += 4) {
            uint32_t v = 0;
#pragma unroll
            for (int k = 0; k < 4; k++) {
                int val = __float2int_rn(xb[(size_t)(c + k) * HWPix]);
                v |= (uint32_t)(val & 0xFF) << (8 * k);
            }
            pk[c >> 2] = v;
        }
        int4* dst = (int4*)(g_x8 + (size_t)p * CIN);
#pragma unroll
        for (int i = 0; i < 8; i++)
            dst[i] = make_int4((int)pk[4*i], (int)pk[4*i+1], (int)pk[4*i+2], (int)pk[4*i+3]);
    } else {
        // v3 entry t = (((nt*9 + tap)*2 + h)*32 + lane); 16B per entry.
        // entry holds frag(kc=2h) in bytes[0:8) and frag(kc=2h+1) in [8:16).
        // frag(kc): v0 byte j = W[n][c=kc*32+4*tig+j], v1 = same with c+16,
        // n = nt*8 + g, g=lane>>2, tig=lane&3.
        int t = (blockIdx.x - 392) * 256 + threadIdx.x;   // 0 .. 18431
        if (t < 32 * KTAPS * 2 * 32) {
            int nt   = t / (KTAPS * 2 * 32);
            int r    = t - nt * (KTAPS * 2 * 32);
            int tap  = r / (2 * 32);
            int r2   = r - tap * (2 * 32);
            int h    = r2 >> 5;
            int lane = r2 & 31;
            int g    = lane >> 2, tig = lane & 3;
            int n    = nt * 8 + g;
            uint32_t vv[4];
#pragma unroll
            for (int q = 0; q < 2; q++) {            // kc = 2h + q
                int kc = 2 * h + q;
                uint32_t v0 = 0, v1 = 0;
#pragma unroll
                for (int j = 0; j < 4; j++) {
                    int c0 = kc * 32 + 4 * tig + j;
                    int val0 = __float2int_rn(w[((size_t)(n * CIN + c0)) * KTAPS + tap]);
                    int val1 = __float2int_rn(w[((size_t)(n * CIN + c0 + 16)) * KTAPS + tap]);
                    v0 |= (uint32_t)(val0 & 0xFF) << (8 * j);
                    v1 |= (uint32_t)(val1 & 0xFF) << (8 * j);
                }
                vv[2*q]   = v0;
                vv[2*q+1] = v1;
            }
            int4* dst = (int4*)(g_wfrag + (size_t)t * 16);
            *dst = make_int4((int)vv[0], (int)vv[1], (int)vv[2], (int)vv[3]);
        }
    }
}

// ---------------------------------------------------------------------------
// Kernel 2: implicit-GEMM conv. CTA tile M=64 x N=256, 256 threads
// (8 warps as 2M x 4N, warp tile 32x64). All 9 A-tap slabs resident in smem.
// Weights v3: 2 contiguous LDG.128 per (tn,tap), software-pipelined one tn
// ahead so mma never waits on a just-issued load. 2 CTAs/SM.
// ---------------------------------------------------------------------------
__device__ __forceinline__ void mma_s8(int* c, const int* a, int b0, int b1) {
    asm volatile(
        "mma.sync.aligned.m16n8k32.row.col.s32.s8.s8.s32 "
        "{%0,%1,%2,%3}, {%4,%5,%6,%7}, {%8,%9}, {%0,%1,%2,%3};\n"
        : "+r"(c[0]), "+r"(c[1]), "+r"(c[2]), "+r"(c[3])
        : "r"(a[0]), "r"(a[1]), "r"(a[2]), "r"(a[3]), "r"(b0), "r"(b1));
}

#define CPA16(dst, src, sz) \
    asm volatile("cp.async.cg.shared.global [%0], [%1], 16, %2;\n" \
                 :: "r"(dst), "l"(src), "r"(sz))

__global__ void __launch_bounds__(256, 2)
conv_mma_kernel(const float* __restrict__ tbias,
                const int*   __restrict__ nshift,
                const int*   __restrict__ amin,
                const int*   __restrict__ amax,
                float*       __restrict__ out) {
    extern __shared__ __align__(16) int8_t smA[];
    const uint32_t smem_u32 = (uint32_t)__cvta_generic_to_shared(smA);

    const int tid  = threadIdx.x;
    const int lane = tid & 31;
    const int warp = tid >> 5;
    const int warpM = warp >> 2;         // 0..1 -> 32 M-rows each
    const int warpN = warp & 3;          // 0..3 -> 64 N-cols (8 n8-tiles)
    const int g   = lane >> 2;
    const int tig = lane & 3;

    const int m0  = blockIdx.x * 64;     // 3136 % 64 == 0 -> tile never spans batch
    const int b   = m0 / HWPix;
    const int hw0 = m0 - b * HWPix;

    // A-loader invariants: row = tid>>2 (0..63), quarter = tid&3 (32B each)
    const int ar = tid >> 2, aq = tid & 3;
    const int ahw = hw0 + ar;
    const int ah  = ahw / WW;
    const int aw  = ahw - ah * WW;

    // ---- issue ALL 9 tap slabs, one commit group per tap ----
#pragma unroll
    for (int tap = 0; tap < KTAPS; tap++) {
        const int dh = tap / 3 - 1;
        const int dw = tap % 3 - 1;
        int hs = ah + dh, ws = aw + dw;
        bool valid = ((unsigned)hs < HH) && ((unsigned)ws < WW);
        int sidx = valid ? (b * HWPix + hs * WW + ws) : 0;
        const int8_t* src = g_x8 + ((size_t)sidx << 7) + aq * 32;
        uint32_t dst = smem_u32 + tap * ABUF + ar * PA + aq * 32;
        int sz = valid ? 16 : 0;
        CPA16(dst,      src,      sz);
        CPA16(dst + 16, src + 16, sz);
        asm volatile("cp.async.commit_group;\n");
    }

    int acc[2][8][4];
#pragma unroll
    for (int i = 0; i < 2; i++)
#pragma unroll
        for (int j = 0; j < 8; j++)
#pragma unroll
            for (int k = 0; k < 4; k++) acc[i][j][k] = 0;

    // W base for this warp: nt = warpN*8 + tn.
    // addr(nt,tap,h) = ((nt*9 + tap)*2 + h)*512 + lane*16
    const int8_t* wbase = g_wfrag + (size_t)(warpN * 8) * (KTAPS * 1024)
                        + (size_t)lane * 16;

    // ---- mainloop over taps ----
#pragma unroll 1
    for (int tap = 0; tap < KTAPS; tap++) {
        // progressive wait: this tap's group has landed when <= (8-tap) pending
        switch (tap) {
            case 0: asm volatile("cp.async.wait_group 8;\n"); break;
            case 1: asm volatile("cp.async.wait_group 7;\n"); break;
            case 2: asm volatile("cp.async.wait_group 6;\n"); break;
            case 3: asm volatile("cp.async.wait_group 5;\n"); break;
            case 4: asm volatile("cp.async.wait_group 4;\n"); break;
            case 5: asm volatile("cp.async.wait_group 3;\n"); break;
            case 6: asm volatile("cp.async.wait_group 2;\n"); break;
            case 7: asm volatile("cp.async.wait_group 1;\n"); break;
            default: asm volatile("cp.async.wait_group 0;\n"); break;
        }
        __syncthreads();    // data visible + keeps warps temporally aligned

        // A fragments for all 4 kc (8 LDSM, 32 regs)
        int a[2][4][4];
        const uint32_t baseA = smem_u32 + tap * ABUF;
#pragma unroll
        for (int mi = 0; mi < 2; mi++) {
#pragma unroll
            for (int kc = 0; kc < 4; kc++) {
                int row = warpM * 32 + mi * 16 + (lane & 15);
                int col = kc * 32 + ((lane >> 4) << 4);
                uint32_t addr = baseA + row * PA + col;
                asm volatile(
                    "ldmatrix.sync.aligned.m8n8.x4.shared.b16 {%0,%1,%2,%3}, [%4];\n"
                    : "=r"(a[mi][kc][0]), "=r"(a[mi][kc][1]),
                      "=r"(a[mi][kc][2]), "=r"(a[mi][kc][3])
                    : "r"(addr));
            }
        }

        // weight-pipelined tn loop: 2 contiguous LDG.128 per tn, depth-1 ahead
        const int8_t* wt = wbase + (size_t)tap * 1024;
        int4 w0 = __ldg((const int4*)(wt));
        int4 w1 = __ldg((const int4*)(wt + 512));
#pragma unroll
        for (int tn = 0; tn < 8; tn++) {
            int4 n0, n1;
            if (tn < 7) {
                const int8_t* wn = wt + (size_t)(tn + 1) * (KTAPS * 1024);
                n0 = __ldg((const int4*)(wn));
                n1 = __ldg((const int4*)(wn + 512));
            }
#pragma unroll
            for (int mi = 0; mi < 2; mi++) {
                mma_s8(acc[mi][tn], a[mi][0], w0.x, w0.y);
                mma_s8(acc[mi][tn], a[mi][1], w0.z, w0.w);
                mma_s8(acc[mi][tn], a[mi][2], w1.x, w1.y);
                mma_s8(acc[mi][tn], a[mi][3], w1.z, w1.w);
            }
            if (tn < 7) { w0 = n0; w1 = n1; }
        }
    }

    // ---- epilogue: bias + arithmetic shift + clamp -> float32 out ----
#pragma unroll
    for (int tn = 0; tn < 8; tn++) {
#pragma unroll
        for (int cb = 0; cb < 2; cb++) {
            int ng = warpN * 64 + tn * 8 + 2 * tig + cb;
            int tb = __float2int_rn(__ldg(&tbias[ng]));
            int sh = -__ldg(&nshift[ng]);
            int mn = __ldg(&amin[ng]);
            int mx = __ldg(&amax[ng]);
            float* rowp = out + ((size_t)b * COUT + ng) * HWPix + hw0;
#pragma unroll
            for (int mi = 0; mi < 2; mi++) {
#pragma unroll
                for (int rh = 0; rh < 2; rh++) {
                    int v = acc[mi][tn][rh * 2 + cb];
                    v = (v + tb) >> sh;
                    v = max(mn, min(mx, v));
                    int ml = warpM * 32 + mi * 16 + rh * 8 + g;
                    rowp[ml] = (float)v;
                }
            }
        }
    }
}

// ---------------------------------------------------------------------------
// Launch
// ---------------------------------------------------------------------------
extern "C" void kernel_launch(void* const* d_in, const int* in_sizes, int n_in,
                              void* d_out, int out_size) {
    const float* x      = (const float*)d_in[0];
    const float* weight = (const float*)d_in[1];
    const float* tbias  = (const float*)d_in[2];
    const int*   nsh    = (const int*)d_in[3];
    const int*   amin   = (const int*)d_in[4];
    const int*   amax   = (const int*)d_in[5];
    float* out = (float*)d_out;

    (void)cudaFuncSetAttribute(conv_mma_kernel,
                               cudaFuncAttributeMaxDynamicSharedMemorySize,
                               SMEMSZ);

    convert_kernel<<<464, 256>>>(x, weight);                       // 392 + 72 blocks
    conv_mma_kernel<<<BATCH * (HWPix / 64), 256, SMEMSZ>>>(tbias, nsh, amin, amax, out);
}

// round 15
// speedup vs baseline: 1.4471x; 1.0731x over previous
#include <cuda_runtime.h>
#include <cstdint>

// Problem constants
#define BATCH 32
#define CIN   128
#define COUT  256
#define HH    56
#define WW    56
#define HWPix (HH*WW)          // 3136
#define KTAPS 9
#define KTOT  (CIN*KTAPS)      // 1152

#define PA 144                 // A smem pitch (bytes), LDSM conflict-free
#define ABUF (64*PA)           // 9216 per tap slab (M=64 tile)
#define SMEMSZ (KTAPS*ABUF)    // 82944 : all 9 tap slabs resident, 2 CTAs/SM

// Scratch (allocation-free rule: __device__ globals)
__device__ __align__(128) int8_t g_x8[(size_t)BATCH * HWPix * CIN];     // NHWC int8
// Weights v3 fragment order: [ntile 32][tap 9][half 2][lane 32] x 16B
// half h covers kc = 2h (bytes 0:8) and kc = 2h+1 (bytes 8:16).
// Warp LDG.128 at (nt,tap,h) + lane*16 is a contiguous 512B request.
__device__ __align__(128) int8_t g_wfrag[32 * KTAPS * 2 * 32 * 16];     // 294912 B

// ---------------------------------------------------------------------------
// Kernel 1: merged converts.
//   blocks [0,392): x fp32 NCHW -> int8 NHWC, thread per pixel.
//   blocks [392,464): w fp32 OIHW -> fragment-ordered int8 (layout v3).
// ---------------------------------------------------------------------------
__global__ void convert_kernel(const float* __restrict__ x,
                               const float* __restrict__ w) {
    if (blockIdx.x < 392) {
        int p  = blockIdx.x * 256 + threadIdx.x;      // 0 .. 100351
        int b  = p / HWPix;
        int hw = p - b * HWPix;
        const float* xb = x + (size_t)b * CIN * HWPix + hw;
        uint32_t pk[32];
#pragma unroll
        for (int c = 0; c < CIN; c += 4) {
            uint32_t v = 0;
#pragma unroll
            for (int k = 0; k < 4; k++) {
                int val = __float2int_rn(xb[(size_t)(c + k) * HWPix]);
                v |= (uint32_t)(val & 0xFF) << (8 * k);
            }
            pk[c >> 2] = v;
        }
        int4* dst = (int4*)(g_x8 + (size_t)p * CIN);
#pragma unroll
        for (int i = 0; i < 8; i++)
            dst[i] = make_int4((int)pk[4*i], (int)pk[4*i+1], (int)pk[4*i+2], (int)pk[4*i+3]);
    } else {
        // v3 entry t = (((nt*9 + tap)*2 + h)*32 + lane); 16B per entry.
        // entry holds frag(kc=2h) in bytes[0:8) and frag(kc=2h+1) in [8:16).
        // frag(kc): v0 byte j = W[n][c=kc*32+4*tig+j], v1 = same with c+16,
        // n = nt*8 + g, g=lane>>2, tig=lane&3.
        int t = (blockIdx.x - 392) * 256 + threadIdx.x;   // 0 .. 18431
        if (t < 32 * KTAPS * 2 * 32) {
            int nt   = t / (KTAPS * 2 * 32);
            int r    = t - nt * (KTAPS * 2 * 32);
            int tap  = r / (2 * 32);
            int r2   = r - tap * (2 * 32);
            int h    = r2 >> 5;
            int lane = r2 & 31;
            int g    = lane >> 2, tig = lane & 3;
            int n    = nt * 8 + g;
            uint32_t vv[4];
#pragma unroll
            for (int q = 0; q < 2; q++) {            // kc = 2h + q
                int kc = 2 * h + q;
                uint32_t v0 = 0, v1 = 0;
#pragma unroll
                for (int j = 0; j < 4; j++) {
                    int c0 = kc * 32 + 4 * tig + j;
                    int val0 = __float2int_rn(w[((size_t)(n * CIN + c0)) * KTAPS + tap]);
                    int val1 = __float2int_rn(w[((size_t)(n * CIN + c0 + 16)) * KTAPS + tap]);
                    v0 |= (uint32_t)(val0 & 0xFF) << (8 * j);
                    v1 |= (uint32_t)(val1 & 0xFF) << (8 * j);
                }
                vv[2*q]   = v0;
                vv[2*q+1] = v1;
            }
            int4* dst = (int4*)(g_wfrag + (size_t)t * 16);
            *dst = make_int4((int)vv[0], (int)vv[1], (int)vv[2], (int)vv[3]);
        }
    }
}

// ---------------------------------------------------------------------------
// Kernel 2: implicit-GEMM conv. CTA tile M=64 x N=256, 256 threads
// (8 warps as 2M x 4N, warp tile 32x64). All 9 A-tap slabs resident in smem;
// single wait + single barrier, then free-running mainloop (no in-loop sync).
// Per half-tap: 4 LDSM + 8 independent LDG.128 (MLP batch), then 32 mmas.
// ---------------------------------------------------------------------------
__device__ __forceinline__ void mma_s8(int* c, const int* a, int b0, int b1) {
    asm volatile(
        "mma.sync.aligned.m16n8k32.row.col.s32.s8.s8.s32 "
        "{%0,%1,%2,%3}, {%4,%5,%6,%7}, {%8,%9}, {%0,%1,%2,%3};\n"
        : "+r"(c[0]), "+r"(c[1]), "+r"(c[2]), "+r"(c[3])
        : "r"(a[0]), "r"(a[1]), "r"(a[2]), "r"(a[3]), "r"(b0), "r"(b1));
}

#define CPA16(dst, src, sz) \
    asm volatile("cp.async.cg.shared.global [%0], [%1], 16, %2;\n" \
                 :: "r"(dst), "l"(src), "r"(sz))

__global__ void __launch_bounds__(256, 2)
conv_mma_kernel(const float* __restrict__ tbias,
                const int*   __restrict__ nshift,
                const int*   __restrict__ amin,
                const int*   __restrict__ amax,
                float*       __restrict__ out) {
    extern __shared__ __align__(16) int8_t smA[];
    const uint32_t smem_u32 = (uint32_t)__cvta_generic_to_shared(smA);

    const int tid  = threadIdx.x;
    const int lane = tid & 31;
    const int warp = tid >> 5;
    const int warpM = warp >> 2;         // 0..1 -> 32 M-rows each
    const int warpN = warp & 3;          // 0..3 -> 64 N-cols (8 n8-tiles)
    const int g   = lane >> 2;
    const int tig = lane & 3;

    const int m0  = blockIdx.x * 64;     // 3136 % 64 == 0 -> tile never spans batch
    const int b   = m0 / HWPix;
    const int hw0 = m0 - b * HWPix;

    // A-loader invariants: row = tid>>2 (0..63), quarter = tid&3 (32B each)
    const int ar = tid >> 2, aq = tid & 3;
    const int ahw = hw0 + ar;
    const int ah  = ahw / WW;
    const int aw  = ahw - ah * WW;

    // ---- load ALL 9 tap slabs up front (single group, single barrier) ----
#pragma unroll
    for (int tap = 0; tap < KTAPS; tap++) {
        const int dh = tap / 3 - 1;
        const int dw = tap % 3 - 1;
        int hs = ah + dh, ws = aw + dw;
        bool valid = ((unsigned)hs < HH) && ((unsigned)ws < WW);
        int sidx = valid ? (b * HWPix + hs * WW + ws) : 0;
        const int8_t* src = g_x8 + ((size_t)sidx << 7) + aq * 32;
        uint32_t dst = smem_u32 + tap * ABUF + ar * PA + aq * 32;
        int sz = valid ? 16 : 0;
        CPA16(dst,      src,      sz);
        CPA16(dst + 16, src + 16, sz);
    }
    asm volatile("cp.async.commit_group;\n");

    int acc[2][8][4];
#pragma unroll
    for (int i = 0; i < 2; i++)
#pragma unroll
        for (int j = 0; j < 8; j++)
#pragma unroll
            for (int k = 0; k < 4; k++) acc[i][j][k] = 0;

    // W base for this warp: nt = warpN*8 + tn.
    // addr(nt,tap,h) = ((nt*9 + tap)*2 + h)*512 + lane*16
    const int8_t* wbase = g_wfrag + (size_t)(warpN * 8) * (KTAPS * 1024)
                        + (size_t)lane * 16;

    asm volatile("cp.async.wait_group 0;\n");
    __syncthreads();      // the ONLY barrier: all slabs visible to all warps

    // ---- mainloop: free-running, per half-tap load batch then 32 mmas ----
#pragma unroll 1
    for (int tap = 0; tap < KTAPS; tap++) {
        const uint32_t baseA = smem_u32 + tap * ABUF;
        const int8_t*  wt    = wbase + (size_t)tap * 1024;
#pragma unroll
        for (int h = 0; h < 2; h++) {
            // A fragments for kc = 2h, 2h+1 (4 LDSM)
            int a[2][2][4];
#pragma unroll
            for (int mi = 0; mi < 2; mi++) {
#pragma unroll
                for (int q = 0; q < 2; q++) {
                    int row = warpM * 32 + mi * 16 + (lane & 15);
                    int col = (2 * h + q) * 32 + ((lane >> 4) << 4);
                    uint32_t addr = baseA + row * PA + col;
                    asm volatile(
                        "ldmatrix.sync.aligned.m8n8.x4.shared.b16 {%0,%1,%2,%3}, [%4];\n"
                        : "=r"(a[mi][q][0]), "=r"(a[mi][q][1]),
                          "=r"(a[mi][q][2]), "=r"(a[mi][q][3])
                        : "r"(addr));
                }
            }
            // 8 independent contiguous LDG.128 (one per tn) — MLP batch
            int4 wv[8];
#pragma unroll
            for (int tn = 0; tn < 8; tn++)
                wv[tn] = __ldg((const int4*)(wt + h * 512 + (size_t)tn * (KTAPS * 1024)));
            // 32 mmas, kc-outer (acc reuse gap = 16)
#pragma unroll
            for (int q = 0; q < 2; q++) {
#pragma unroll
                for (int tn = 0; tn < 8; tn++) {
                    int b0 = q ? wv[tn].z : wv[tn].x;
                    int b1 = q ? wv[tn].w : wv[tn].y;
                    mma_s8(acc[0][tn], a[0][q], b0, b1);
                    mma_s8(acc[1][tn], a[1][q], b0, b1);
                }
            }
        }
    }

    // ---- epilogue: bias + arithmetic shift + clamp -> float32 out ----
#pragma unroll
    for (int tn = 0; tn < 8; tn++) {
#pragma unroll
        for (int cb = 0; cb < 2; cb++) {
            int ng = warpN * 64 + tn * 8 + 2 * tig + cb;
            int tb = __float2int_rn(__ldg(&tbias[ng]));
            int sh = -__ldg(&nshift[ng]);
            int mn = __ldg(&amin[ng]);
            int mx = __ldg(&amax[ng]);
            float* rowp = out + ((size_t)b * COUT + ng) * HWPix + hw0;
#pragma unroll
            for (int mi = 0; mi < 2; mi++) {
#pragma unroll
                for (int rh = 0; rh < 2; rh++) {
                    int v = acc[mi][tn][rh * 2 + cb];
                    v = (v + tb) >> sh;
                    v = max(mn, min(mx, v));
                    int ml = warpM * 32 + mi * 16 + rh * 8 + g;
                    rowp[ml] = (float)v;
                }
            }
        }
    }
}

// ---------------------------------------------------------------------------
// Launch
// ---------------------------------------------------------------------------
extern "C" void kernel_launch(void* const* d_in, const int* in_sizes, int n_in,
                              void* d_out, int out_size) {
    const float* x      = (const float*)d_in[0];
    const float* weight = (const float*)d_in[1];
    const float* tbias  = (const float*)d_in[2];
    const int*   nsh    = (const int*)d_in[3];
    const int*   amin   = (const int*)d_in[4];
    const int*   amax   = (const int*)d_in[5];
    float* out = (float*)d_out;

    (void)cudaFuncSetAttribute(conv_mma_kernel,
                               cudaFuncAttributeMaxDynamicSharedMemorySize,
                               SMEMSZ);

    convert_kernel<<<464, 256>>>(x, weight);                       // 392 + 72 blocks
    conv_mma_kernel<<<BATCH * (HWPix / 64), 256, SMEMSZ>>>(tbias, nsh, amin, amax, out);
}